// round 15
// baseline (speedup 1.0000x reference)
#include <cuda_runtime.h>
#include <cuda_bf16.h>
#include <cstddef>
#include <cstdint>

// Problem constants
#define BB   64
#define TT   2048
#define HH   128
#define GG   384     // 3*H
#define DIN  18
#define DOUT 2
#define BTR  (BB*TT)           // 131072 rows
#define GK   256               // layer-1 input width

typedef unsigned long long u64;

// ---------------------------------------------------------------------------
// Scratch (device globals; no allocation allowed)
// ---------------------------------------------------------------------------
static __device__ float          g_xgF[(size_t)BTR * GG];   // 201 MB
static __device__ float          g_xgR[(size_t)BTR * GG];   // 201 MB
static __device__ unsigned short g_hHi[(size_t)BTR * 256];  // 67 MB (bf16 hi plane)
static __device__ unsigned short g_hLo[(size_t)BTR * 256];  // 67 MB (bf16 lo plane)

// ---------------------------------------------------------------------------
// Helpers
// ---------------------------------------------------------------------------
__device__ __forceinline__ u64 ffma2(u64 a, u64 b, u64 c) {
    u64 d;
    asm("fma.rn.f32x2 %0, %1, %2, %3;" : "=l"(d) : "l"(a), "l"(b), "l"(c));
    return d;
}
__device__ __forceinline__ u64 addf2(u64 a, u64 b) {
    u64 d;
    asm("add.rn.f32x2 %0, %1, %2;" : "=l"(d) : "l"(a), "l"(b));
    return d;
}
__device__ __forceinline__ u64 d2u(double x) {
    return (u64)__double_as_longlong(x);
}
__device__ __forceinline__ float2 unpack2(u64 v) {
    float2 r;
    asm("mov.b64 {%0, %1}, %2;" : "=f"(r.x), "=f"(r.y) : "l"(v));
    return r;
}
__device__ __forceinline__ float sigf(float x) {
    return 1.0f / (1.0f + __expf(-x));
}
__device__ __forceinline__ float tanh_fast(float x) {
    float xc = fminf(fmaxf(x, -20.0f), 20.0f);
    float e  = __expf(-2.0f * xc);
    return (1.0f - e) / (1.0f + e);
}
__device__ __forceinline__ uint32_t smem_u32(const void* p) {
    uint32_t a;
    asm("{ .reg .u64 t; cvta.to.shared.u64 t, %1; cvt.u32.u64 %0, t; }" : "=r"(a) : "l"(p));
    return a;
}
#define CP_ASYNC16(dst, src) \
    asm volatile("cp.async.cg.shared.global [%0], [%1], 16;" :: "r"(dst), "l"(src) : "memory")
#define CP_COMMIT() asm volatile("cp.async.commit_group;" ::: "memory")
#define CP_WAIT(n)  asm volatile("cp.async.wait_group %0;" :: "n"(n) : "memory")

// ---------------------------------------------------------------------------
// Generic fp32 GEMM (K=18 projections): C[M][N] = A[M][K]*B[N][K]^T + bias[N]
// ---------------------------------------------------------------------------
__global__ __launch_bounds__(256) void gemm_tn_bias(
    const float* __restrict__ A, int lda,
    const float* __restrict__ Bw,
    const float* __restrict__ bias,
    float* __restrict__ C, int ldc,
    int M, int N, int K)
{
    const int BM = 64, BN = 64, BK = 16;
    const int PAD = 8;
    __shared__ __align__(16) float As[BK][BM + PAD];
    __shared__ __align__(16) float Bs[BK][BN + PAD];

    int tid = threadIdx.x;
    int tx = tid & 15;
    int ty = tid >> 4;
    int m0 = blockIdx.x * BM;
    int n0 = blockIdx.y * BN;

    float acc[4][4];
#pragma unroll
    for (int i = 0; i < 4; i++)
#pragma unroll
        for (int j = 0; j < 4; j++) acc[i][j] = 0.0f;

    int nkt = (K + BK - 1) / BK;
    for (int kt = 0; kt < nkt; kt++) {
        int k0 = kt * BK;
#pragma unroll
        for (int r = 0; r < 4; r++) {
            int idx = tid + r * 256;
            int m = idx >> 4;
            int k = idx & 15;
            float va = 0.0f, vb = 0.0f;
            if (k0 + k < K) {
                va = A[(size_t)(m0 + m) * lda + k0 + k];
                vb = Bw[(size_t)(n0 + m) * K + k0 + k];
            }
            As[k][m] = va;
            Bs[k][m] = vb;
        }
        __syncthreads();
#pragma unroll
        for (int k = 0; k < BK; k++) {
            float4 a = *(const float4*)&As[k][ty * 4];
            float4 b = *(const float4*)&Bs[k][tx * 4];
            float av[4] = {a.x, a.y, a.z, a.w};
            float bv[4] = {b.x, b.y, b.z, b.w};
#pragma unroll
            for (int i = 0; i < 4; i++)
#pragma unroll
                for (int j = 0; j < 4; j++)
                    acc[i][j] = fmaf(av[i], bv[j], acc[i][j]);
        }
        __syncthreads();
    }

    float4 bv = *(const float4*)&bias[n0 + tx * 4];
#pragma unroll
    for (int i = 0; i < 4; i++) {
        int m = m0 + ty * 4 + i;
        float4 o = make_float4(acc[i][0] + bv.x, acc[i][1] + bv.y,
                               acc[i][2] + bv.z, acc[i][3] + bv.w);
        __stcs((float4*)&C[(size_t)m * ldc + n0 + tx * 4], o);
    }
}

// ---------------------------------------------------------------------------
// Tensor-core GEMM via mma.sync (K=256): C[BTR][384] = A * W^T + bias
// A planes double-buffered via cp.async (DRAM latency hidden under MMA);
// W loaded+split in-line (L2-hot). Fragments reused across the 3 terms.
// smem: A 2buf x 2planes + W 2planes of [128][72] bf16.
// ---------------------------------------------------------------------------
#define SA 72
#define SM_PLANE (128 * SA * 2)     // 18432 bytes per plane
__global__ __launch_bounds__(256, 2) void hmma_gemm(
    const unsigned short* __restrict__ Ahi,
    const unsigned short* __restrict__ Alo,
    const float* __restrict__ W,      // [384][256]
    const float* __restrict__ bias,   // [384]
    float* __restrict__ C)            // [BTR][384]
{
    extern __shared__ __align__(16) unsigned short smh[];
    // layout: [buf0 Ahi][buf0 Alo][buf1 Ahi][buf1 Alo][Whi][Wlo]
    unsigned short* sWhi = smh + 4 * 128 * SA;
    unsigned short* sWlo = sWhi + 128 * SA;

    int tid  = threadIdx.x;
    int lane = tid & 31;
    int warp = tid >> 5;
    size_t m0 = (size_t)blockIdx.x * 128;
    int    n0 = blockIdx.y * 128;
    int m_off = (warp & 1) * 64;
    int n_off = (warp >> 1) * 32;

    float acc[4][4][4];     // [mt][nt][frag]
#pragma unroll
    for (int a = 0; a < 4; a++)
#pragma unroll
        for (int b = 0; b < 4; b++)
#pragma unroll
            for (int c = 0; c < 4; c++) acc[a][b][c] = 0.0f;

    // Loader indices
    int r  = tid >> 1;            // 0..127
    int c0 = (tid & 1) * 32;      // 0 or 32
    const size_t arow = (m0 + r) * GK;
    const size_t wrow = (size_t)(n0 + r) * GK;

    uint32_t sb = smem_u32(smh);
    uint32_t aSmemRow = (uint32_t)(r * SA + c0) * 2;   // byte offset within a plane

    // ldmatrix per-lane address components (element units)
    int ln  = lane & 7;
    int sel = lane >> 3;
    int aoff = (m_off + ln + (sel & 1) * 8) * SA + (sel >> 1) * 8;
    int half = (lane >> 3) & 1;
    int boff = (n_off + (lane & 7)) * SA + half * 8;

    // Prologue: cp.async A chunk 0 into buf 0
#pragma unroll
    for (int i = 0; i < 4; i++) {
        CP_ASYNC16(sb + 0 * SM_PLANE + aSmemRow + 16 * i, &Ahi[arow + c0 + 8 * i]);
        CP_ASYNC16(sb + 1 * SM_PLANE + aSmemRow + 16 * i, &Alo[arow + c0 + 8 * i]);
    }
    CP_COMMIT();

    for (int ch = 0; ch < 4; ch++) {
        int kb = ch * 64 + c0;
        int buf = ch & 1;

        // cp.async next chunk's A into the other buffer
        if (ch < 3) {
            int kb2 = (ch + 1) * 64 + c0;
            uint32_t nb = sb + ((ch + 1) & 1) * 2 * SM_PLANE + aSmemRow;
#pragma unroll
            for (int i = 0; i < 4; i++) {
                CP_ASYNC16(nb + 16 * i,            &Ahi[arow + kb2 + 8 * i]);
                CP_ASYNC16(nb + SM_PLANE + 16 * i, &Alo[arow + kb2 + 8 * i]);
            }
        }
        CP_COMMIT();

        // W: LDG + hi/lo split + STS (single buffer)
#pragma unroll
        for (int i = 0; i < 8; i++) {
            float4 wv = *(const float4*)&W[wrow + kb + 4 * i];
            __nv_bfloat16 h0 = __float2bfloat16(wv.x);
            __nv_bfloat16 h1 = __float2bfloat16(wv.y);
            __nv_bfloat16 h2 = __float2bfloat16(wv.z);
            __nv_bfloat16 h3 = __float2bfloat16(wv.w);
            __nv_bfloat16 l0 = __float2bfloat16(wv.x - __bfloat162float(h0));
            __nv_bfloat16 l1 = __float2bfloat16(wv.y - __bfloat162float(h1));
            __nv_bfloat16 l2 = __float2bfloat16(wv.z - __bfloat162float(h2));
            __nv_bfloat16 l3 = __float2bfloat16(wv.w - __bfloat162float(h3));
            uint2 uh, ul;
            uh.x = (uint32_t)__bfloat16_as_ushort(h0) | ((uint32_t)__bfloat16_as_ushort(h1) << 16);
            uh.y = (uint32_t)__bfloat16_as_ushort(h2) | ((uint32_t)__bfloat16_as_ushort(h3) << 16);
            ul.x = (uint32_t)__bfloat16_as_ushort(l0) | ((uint32_t)__bfloat16_as_ushort(l1) << 16);
            ul.y = (uint32_t)__bfloat16_as_ushort(l2) | ((uint32_t)__bfloat16_as_ushort(l3) << 16);
            *(uint2*)&sWhi[r * SA + c0 + 4 * i] = uh;
            *(uint2*)&sWlo[r * SA + c0 + 4 * i] = ul;
        }

        // Wait for this chunk's A (1 group -- next chunk's -- may stay pending)
        if (ch < 3) { CP_WAIT(1); } else { CP_WAIT(0); }
        __syncthreads();

        uint32_t aHiBase = sb + buf * 2 * SM_PLANE;
        uint32_t aLoBase = aHiBase + SM_PLANE;

#pragma unroll
        for (int kk = 0; kk < 4; kk++) {
            uint32_t afh[4][4], afl[4][4], bfr[4][2];
#pragma unroll
            for (int mt = 0; mt < 4; mt++) {
                uint32_t addr = aHiBase + (uint32_t)(aoff + mt * 16 * SA + kk * 16) * 2;
                asm volatile(
                    "ldmatrix.sync.aligned.m8n8.x4.shared.b16 {%0,%1,%2,%3}, [%4];"
                    : "=r"(afh[mt][0]), "=r"(afh[mt][1]), "=r"(afh[mt][2]), "=r"(afh[mt][3])
                    : "r"(addr));
            }
#pragma unroll
            for (int nt = 0; nt < 4; nt++) {
                uint32_t addr = sb + 4 * SM_PLANE + (uint32_t)(boff + nt * 8 * SA + kk * 16) * 2;
                asm volatile(
                    "ldmatrix.sync.aligned.m8n8.x2.shared.b16 {%0,%1}, [%2];"
                    : "=r"(bfr[nt][0]), "=r"(bfr[nt][1]) : "r"(addr));
            }
            // term: Ahi * Whi
#pragma unroll
            for (int mt = 0; mt < 4; mt++)
#pragma unroll
                for (int nt = 0; nt < 4; nt++)
                    asm volatile(
                        "mma.sync.aligned.m16n8k16.row.col.f32.bf16.bf16.f32 "
                        "{%0,%1,%2,%3}, {%4,%5,%6,%7}, {%8,%9}, {%0,%1,%2,%3};"
                        : "+f"(acc[mt][nt][0]), "+f"(acc[mt][nt][1]),
                          "+f"(acc[mt][nt][2]), "+f"(acc[mt][nt][3])
                        : "r"(afh[mt][0]), "r"(afh[mt][1]), "r"(afh[mt][2]), "r"(afh[mt][3]),
                          "r"(bfr[nt][0]), "r"(bfr[nt][1]));
            // Alo fragments
#pragma unroll
            for (int mt = 0; mt < 4; mt++) {
                uint32_t addr = aLoBase + (uint32_t)(aoff + mt * 16 * SA + kk * 16) * 2;
                asm volatile(
                    "ldmatrix.sync.aligned.m8n8.x4.shared.b16 {%0,%1,%2,%3}, [%4];"
                    : "=r"(afl[mt][0]), "=r"(afl[mt][1]), "=r"(afl[mt][2]), "=r"(afl[mt][3])
                    : "r"(addr));
            }
            // term: Alo * Whi (reuses bfr)
#pragma unroll
            for (int mt = 0; mt < 4; mt++)
#pragma unroll
                for (int nt = 0; nt < 4; nt++)
                    asm volatile(
                        "mma.sync.aligned.m16n8k16.row.col.f32.bf16.bf16.f32 "
                        "{%0,%1,%2,%3}, {%4,%5,%6,%7}, {%8,%9}, {%0,%1,%2,%3};"
                        : "+f"(acc[mt][nt][0]), "+f"(acc[mt][nt][1]),
                          "+f"(acc[mt][nt][2]), "+f"(acc[mt][nt][3])
                        : "r"(afl[mt][0]), "r"(afl[mt][1]), "r"(afl[mt][2]), "r"(afl[mt][3]),
                          "r"(bfr[nt][0]), "r"(bfr[nt][1]));
            // Wlo fragments (overwrite bfr; Whi dead)
#pragma unroll
            for (int nt = 0; nt < 4; nt++) {
                uint32_t addr = sb + 5 * SM_PLANE + (uint32_t)(boff + nt * 8 * SA + kk * 16) * 2;
                asm volatile(
                    "ldmatrix.sync.aligned.m8n8.x2.shared.b16 {%0,%1}, [%2];"
                    : "=r"(bfr[nt][0]), "=r"(bfr[nt][1]) : "r"(addr));
            }
            // term: Ahi * Wlo
#pragma unroll
            for (int mt = 0; mt < 4; mt++)
#pragma unroll
                for (int nt = 0; nt < 4; nt++)
                    asm volatile(
                        "mma.sync.aligned.m16n8k16.row.col.f32.bf16.bf16.f32 "
                        "{%0,%1,%2,%3}, {%4,%5,%6,%7}, {%8,%9}, {%0,%1,%2,%3};"
                        : "+f"(acc[mt][nt][0]), "+f"(acc[mt][nt][1]),
                          "+f"(acc[mt][nt][2]), "+f"(acc[mt][nt][3])
                        : "r"(afh[mt][0]), "r"(afh[mt][1]), "r"(afh[mt][2]), "r"(afh[mt][3]),
                          "r"(bfr[nt][0]), "r"(bfr[nt][1]));
        }
        __syncthreads();   // W planes / A buffer reuse safe after all LDSM done
    }

    // Epilogue (streaming stores; xg is read-once later)
    int cr  = lane >> 2;
    int cc2 = (lane & 3) * 2;
#pragma unroll
    for (int nt = 0; nt < 4; nt++) {
        int n = n0 + n_off + nt * 8 + cc2;
        float2 bq = *(const float2*)&bias[n];
#pragma unroll
        for (int mt = 0; mt < 4; mt++) {
            size_t m = m0 + m_off + mt * 16 + cr;
            float2 o0 = make_float2(acc[mt][nt][0] + bq.x, acc[mt][nt][1] + bq.y);
            float2 o1 = make_float2(acc[mt][nt][2] + bq.x, acc[mt][nt][3] + bq.y);
            __stcs((float2*)&C[m * GG + n],       o0);
            __stcs((float2*)&C[(m + 8) * GG + n], o1);
        }
    }
}

// ---------------------------------------------------------------------------
// GRU scan: role-structured, RACE-FREE two-__syncthreads protocol (R8 semantics),
// f32x2 reduction tree. grid = 128, 384 threads.
// g<256: r/z producer; g>=256: n gate + h update.
// ---------------------------------------------------------------------------
__global__ __launch_bounds__(384, 1) void gru_scan(
    const float* __restrict__ xgF, const float* __restrict__ xgR,
    const float* __restrict__ whhF, const float* __restrict__ bhhF,
    const float* __restrict__ whhR, const float* __restrict__ bhhR,
    unsigned short* __restrict__ outHi, unsigned short* __restrict__ outLo)
{
    int bb  = blockIdx.x >> 1;
    int dir = blockIdx.x & 1;
    const float* xg  = dir ? xgR  : xgF;
    const float* whh = dir ? whhR : whhF;
    const float* bhh = dir ? bhhR : bhhF;

    int g = threadIdx.x;
    int j = g & 127;

    u64 w2[64];
    {
        const double2* wrow = (const double2*)(whh + (size_t)g * HH);
#pragma unroll
        for (int i = 0; i < 32; i++) {
            double2 v = wrow[i];
            w2[2*i+0] = d2u(v.x);
            w2[2*i+1] = d2u(v.y);
        }
    }
    float bh = bhh[g];

    __shared__ __align__(16) float hs[HH];
    __shared__ float rz[2 * HH];
    if (g < HH) hs[g] = 0.0f;

    const float* xp = xg + (size_t)bb * TT * GG + (size_t)(dir ? (TT - 1) : 0) * GG + g;
    const ptrdiff_t xstep = dir ? -(ptrdiff_t)GG : (ptrdiff_t)GG;

    size_t oidx = (size_t)bb * TT * 256 + (size_t)(dir ? (TT - 1) : 0) * 256
                + (size_t)dir * HH + j;
    const ptrdiff_t ostep = dir ? -(ptrdiff_t)256 : (ptrdiff_t)256;

    float xv = __ldg(xp);
    xp += xstep;
    __syncthreads();

    const double2* hsd = (const double2*)hs;
    bool is_rz = (g < 2 * HH);

    for (int t = 0; t < TT; t++) {
        const float* xpn = (t + 1 < TT) ? xp : (xp - xstep);
        float xv_next = __ldg(xpn);

        u64 a0 = 0ull, a1 = 0ull, a2 = 0ull, a3 = 0ull;
#pragma unroll
        for (int i = 0; i < 16; i++) {
            double2 h0 = hsd[2*i];
            double2 h1 = hsd[2*i+1];
            a0 = ffma2(w2[4*i+0], d2u(h0.x), a0);
            a1 = ffma2(w2[4*i+1], d2u(h0.y), a1);
            a2 = ffma2(w2[4*i+2], d2u(h1.x), a2);
            a3 = ffma2(w2[4*i+3], d2u(h1.y), a3);
        }
        u64 s = addf2(addf2(a0, a1), addf2(a2, a3));
        float2 sp = unpack2(s);
        float acc = sp.x + sp.y + bh;

        if (is_rz) {
            rz[g] = sigf(acc + xv);
        }
        __syncthreads();   // rz visible to n-threads

        if (!is_rz) {
            float r  = rz[j];
            float z  = rz[j + HH];
            float n  = tanh_fast(fmaf(r, acc, xv));   // xv = xn here
            float hp = hs[j];
            float hn = fmaf(z, hp - n, n);
            hs[j] = hn;
            __nv_bfloat16 bhi = __float2bfloat16(hn);
            __nv_bfloat16 blo = __float2bfloat16(hn - __bfloat162float(bhi));
            outHi[oidx] = __bfloat16_as_ushort(bhi);
            outLo[oidx] = __bfloat16_as_ushort(blo);
        }
        __syncthreads();   // hs visible to ALL threads for next matvec

        xv = xv_next;
        xp += xstep;
        oidx += ostep;
    }
}

// ---------------------------------------------------------------------------
// Final FC: reads h1 = hi + lo planes
// ---------------------------------------------------------------------------
__global__ __launch_bounds__(256) void fc_kernel(
    const unsigned short* __restrict__ hHi,
    const unsigned short* __restrict__ hLo,
    const float* __restrict__ fw,   // [2][256]
    const float* __restrict__ fb,   // [2]
    float* __restrict__ out)        // [rows][2]
{
    int row  = blockIdx.x * 8 + (threadIdx.x >> 5);
    int lane = threadIdx.x & 31;
    size_t base = (size_t)row * 256;
    float a0 = 0.f, a1 = 0.f;
#pragma unroll
    for (int i = 0; i < 8; i++) {
        int k = lane + 32 * i;
        float v = __bfloat162float(__ushort_as_bfloat16(hHi[base + k]))
                + __bfloat162float(__ushort_as_bfloat16(hLo[base + k]));
        a0 = fmaf(v, fw[k],       a0);
        a1 = fmaf(v, fw[256 + k], a1);
    }
#pragma unroll
    for (int off = 16; off; off >>= 1) {
        a0 += __shfl_xor_sync(0xffffffffu, a0, off);
        a1 += __shfl_xor_sync(0xffffffffu, a1, off);
    }
    if (lane == 0) {
        out[(size_t)row * 2 + 0] = a0 + fb[0];
        out[(size_t)row * 2 + 1] = a1 + fb[1];
    }
}

// ---------------------------------------------------------------------------
// Launch
// ---------------------------------------------------------------------------
extern "C" void kernel_launch(void* const* d_in, const int* in_sizes, int n_in,
                              void* d_out, int out_size)
{
    const float* x        = (const float*)d_in[0];
    const float* w_ih_l0  = (const float*)d_in[1];
    const float* w_hh_l0  = (const float*)d_in[2];
    const float* b_ih_l0  = (const float*)d_in[3];
    const float* b_hh_l0  = (const float*)d_in[4];
    const float* w_ih_l0r = (const float*)d_in[5];
    const float* w_hh_l0r = (const float*)d_in[6];
    const float* b_ih_l0r = (const float*)d_in[7];
    const float* b_hh_l0r = (const float*)d_in[8];
    const float* w_ih_l1  = (const float*)d_in[9];
    const float* w_hh_l1  = (const float*)d_in[10];
    const float* b_ih_l1  = (const float*)d_in[11];
    const float* b_hh_l1  = (const float*)d_in[12];
    const float* w_ih_l1r = (const float*)d_in[13];
    const float* w_hh_l1r = (const float*)d_in[14];
    const float* b_ih_l1r = (const float*)d_in[15];
    const float* b_hh_l1r = (const float*)d_in[16];
    const float* fc_w     = (const float*)d_in[17];
    const float* fc_b     = (const float*)d_in[18];
    float* out = (float*)d_out;

    float *xgF, *xgR;
    unsigned short *hHi, *hLo;
    cudaGetSymbolAddress((void**)&xgF, g_xgF);
    cudaGetSymbolAddress((void**)&xgR, g_xgR);
    cudaGetSymbolAddress((void**)&hHi, g_hHi);
    cudaGetSymbolAddress((void**)&hLo, g_hLo);

    static int smem_set = 0;
    const int HM_SMEM = 6 * SM_PLANE;   // 110592 B (A 2buf x 2planes + W 2planes)
    if (!smem_set) {
        cudaFuncSetAttribute(hmma_gemm, cudaFuncAttributeMaxDynamicSharedMemorySize, HM_SMEM);
        smem_set = 1;
    }

    // Layer 0 input projections (K = 18)
    dim3 gGrid(BTR / 64, GG / 64);
    gemm_tn_bias<<<gGrid, 256>>>(x, DIN, w_ih_l0,  b_ih_l0,  xgF, GG, BTR, GG, DIN);
    gemm_tn_bias<<<gGrid, 256>>>(x, DIN, w_ih_l0r, b_ih_l0r, xgR, GG, BTR, GG, DIN);

    // Layer 0 scan -> h0 bf16 hi/lo planes
    gru_scan<<<BB * 2, GG>>>(xgF, xgR, w_hh_l0, b_hh_l0, w_hh_l0r, b_hh_l0r, hHi, hLo);

    // Layer 1 input projections (K = 256): tensor-core GEMM via mma.sync
    dim3 tcGrid(BTR / 128, GG / 128);  // 1024 x 3
    hmma_gemm<<<tcGrid, 256, HM_SMEM>>>(hHi, hLo, w_ih_l1,  b_ih_l1,  xgF);
    hmma_gemm<<<tcGrid, 256, HM_SMEM>>>(hHi, hLo, w_ih_l1r, b_ih_l1r, xgR);

    // Layer 1 scan -> h1 planes
    gru_scan<<<BB * 2, GG>>>(xgF, xgR, w_hh_l1, b_hh_l1, w_hh_l1r, b_hh_l1r, hHi, hLo);

    // Final FC
    fc_kernel<<<BTR / 8, 256>>>(hHi, hLo, fc_w, fc_b, out);
}

// round 17
// speedup vs baseline: 1.0383x; 1.0383x over previous
#include <cuda_runtime.h>
#include <cuda_bf16.h>
#include <cstddef>
#include <cstdint>

// Problem constants
#define BB   64
#define TT   2048
#define HH   128
#define GG   384     // 3*H
#define DIN  18
#define DOUT 2
#define BTR  (BB*TT)           // 131072 rows
#define GK   256               // layer-1 input width
#define WN   (GG*GK)           // 98304 weights per direction

typedef unsigned long long u64;

// ---------------------------------------------------------------------------
// Scratch (device globals; no allocation allowed)
// xg buffers have one guard row at each end: logical base = raw + GG.
// ---------------------------------------------------------------------------
static __device__ float          g_xgF_raw[(size_t)(BTR + 2) * GG];
static __device__ float          g_xgR_raw[(size_t)(BTR + 2) * GG];
static __device__ unsigned short g_hHi[(size_t)BTR * 256];  // bf16 hi plane
static __device__ unsigned short g_hLo[(size_t)BTR * 256];  // bf16 lo plane
static __device__ unsigned short g_wHi[2 * WN];             // W hi planes (F,R)
static __device__ unsigned short g_wLo[2 * WN];             // W lo planes (F,R)

// ---------------------------------------------------------------------------
// Helpers
// ---------------------------------------------------------------------------
__device__ __forceinline__ u64 ffma2(u64 a, u64 b, u64 c) {
    u64 d;
    asm("fma.rn.f32x2 %0, %1, %2, %3;" : "=l"(d) : "l"(a), "l"(b), "l"(c));
    return d;
}
__device__ __forceinline__ u64 addf2(u64 a, u64 b) {
    u64 d;
    asm("add.rn.f32x2 %0, %1, %2;" : "=l"(d) : "l"(a), "l"(b));
    return d;
}
__device__ __forceinline__ u64 d2u(double x) {
    return (u64)__double_as_longlong(x);
}
__device__ __forceinline__ float2 unpack2(u64 v) {
    float2 r;
    asm("mov.b64 {%0, %1}, %2;" : "=f"(r.x), "=f"(r.y) : "l"(v));
    return r;
}
__device__ __forceinline__ float sigf(float x) {
    return 1.0f / (1.0f + __expf(-x));
}
__device__ __forceinline__ float tanh_fast(float x) {
    float xc = fminf(fmaxf(x, -20.0f), 20.0f);
    float e  = __expf(-2.0f * xc);
    return (1.0f - e) / (1.0f + e);
}
__device__ __forceinline__ uint32_t smem_u32(const void* p) {
    uint32_t a;
    asm("{ .reg .u64 t; cvta.to.shared.u64 t, %1; cvt.u32.u64 %0, t; }" : "=r"(a) : "l"(p));
    return a;
}
#define CP_ASYNC16(dst, src) \
    asm volatile("cp.async.cg.shared.global [%0], [%1], 16;" :: "r"(dst), "l"(src) : "memory")
#define CP_COMMIT() asm volatile("cp.async.commit_group;" ::: "memory")
#define CP_WAIT(n)  asm volatile("cp.async.wait_group %0;" :: "n"(n) : "memory")

// ---------------------------------------------------------------------------
// W split: fp32 -> bf16 hi/lo planes (one-time, both directions)
// ---------------------------------------------------------------------------
__global__ __launch_bounds__(256) void wsplit(
    const float* __restrict__ WF, const float* __restrict__ WR,
    unsigned short* __restrict__ hi, unsigned short* __restrict__ lo)
{
    int idx = blockIdx.x * 256 + threadIdx.x;   // 0..WN-1
    {
        float w = WF[idx];
        __nv_bfloat16 h = __float2bfloat16(w);
        __nv_bfloat16 l = __float2bfloat16(w - __bfloat162float(h));
        hi[idx] = __bfloat16_as_ushort(h);
        lo[idx] = __bfloat16_as_ushort(l);
    }
    {
        float w = WR[idx];
        __nv_bfloat16 h = __float2bfloat16(w);
        __nv_bfloat16 l = __float2bfloat16(w - __bfloat162float(h));
        hi[WN + idx] = __bfloat16_as_ushort(h);
        lo[WN + idx] = __bfloat16_as_ushort(l);
    }
}

// ---------------------------------------------------------------------------
// Generic fp32 GEMM (K=18 projections): C[M][N] = A[M][K]*B[N][K]^T + bias[N]
// ---------------------------------------------------------------------------
__global__ __launch_bounds__(256) void gemm_tn_bias(
    const float* __restrict__ A, int lda,
    const float* __restrict__ Bw,
    const float* __restrict__ bias,
    float* __restrict__ C, int ldc,
    int M, int N, int K)
{
    const int BM = 64, BN = 64, BK = 16;
    const int PAD = 8;
    __shared__ __align__(16) float As[BK][BM + PAD];
    __shared__ __align__(16) float Bs[BK][BN + PAD];

    int tid = threadIdx.x;
    int tx = tid & 15;
    int ty = tid >> 4;
    int m0 = blockIdx.x * BM;
    int n0 = blockIdx.y * BN;

    float acc[4][4];
#pragma unroll
    for (int i = 0; i < 4; i++)
#pragma unroll
        for (int j = 0; j < 4; j++) acc[i][j] = 0.0f;

    int nkt = (K + BK - 1) / BK;
    for (int kt = 0; kt < nkt; kt++) {
        int k0 = kt * BK;
#pragma unroll
        for (int r = 0; r < 4; r++) {
            int idx = tid + r * 256;
            int m = idx >> 4;
            int k = idx & 15;
            float va = 0.0f, vb = 0.0f;
            if (k0 + k < K) {
                va = A[(size_t)(m0 + m) * lda + k0 + k];
                vb = Bw[(size_t)(n0 + m) * K + k0 + k];
            }
            As[k][m] = va;
            Bs[k][m] = vb;
        }
        __syncthreads();
#pragma unroll
        for (int k = 0; k < BK; k++) {
            float4 a = *(const float4*)&As[k][ty * 4];
            float4 b = *(const float4*)&Bs[k][tx * 4];
            float av[4] = {a.x, a.y, a.z, a.w};
            float bv[4] = {b.x, b.y, b.z, b.w};
#pragma unroll
            for (int i = 0; i < 4; i++)
#pragma unroll
                for (int j = 0; j < 4; j++)
                    acc[i][j] = fmaf(av[i], bv[j], acc[i][j]);
        }
        __syncthreads();
    }

    float4 bv = *(const float4*)&bias[n0 + tx * 4];
#pragma unroll
    for (int i = 0; i < 4; i++) {
        int m = m0 + ty * 4 + i;
        float4 o = make_float4(acc[i][0] + bv.x, acc[i][1] + bv.y,
                               acc[i][2] + bv.z, acc[i][3] + bv.w);
        __stcs((float4*)&C[(size_t)m * ldc + n0 + tx * 4], o);
    }
}

// ---------------------------------------------------------------------------
// Tensor-core GEMM via mma.sync (K=256): C[BTR][384] = A * W^T + bias
// A planes double-buffered via cp.async; W pre-split bf16 planes (plain LDG+STS,
// no per-chunk cvt work). Fragments reused across the 3 terms.
// smem: A 2buf x 2planes + W 2planes of [128][72] bf16.
// ---------------------------------------------------------------------------
#define SA 72
#define SM_PLANE (128 * SA * 2)     // 18432 bytes per plane
__global__ __launch_bounds__(256, 2) void hmma_gemm(
    const unsigned short* __restrict__ Ahi,
    const unsigned short* __restrict__ Alo,
    const unsigned short* __restrict__ Whi,   // [384][256] bf16
    const unsigned short* __restrict__ Wlo,   // [384][256] bf16
    const float* __restrict__ bias,           // [384]
    float* __restrict__ C)                    // [BTR][384]
{
    extern __shared__ __align__(16) unsigned short smh[];
    // layout: [buf0 Ahi][buf0 Alo][buf1 Ahi][buf1 Alo][Whi][Wlo]
    unsigned short* sWhi = smh + 4 * 128 * SA;
    unsigned short* sWlo = sWhi + 128 * SA;

    int tid  = threadIdx.x;
    int lane = tid & 31;
    int warp = tid >> 5;
    size_t m0 = (size_t)blockIdx.x * 128;
    int    n0 = blockIdx.y * 128;
    int m_off = (warp & 1) * 64;
    int n_off = (warp >> 1) * 32;

    float acc[4][4][4];     // [mt][nt][frag]
#pragma unroll
    for (int a = 0; a < 4; a++)
#pragma unroll
        for (int b = 0; b < 4; b++)
#pragma unroll
            for (int c = 0; c < 4; c++) acc[a][b][c] = 0.0f;

    // Loader indices
    int r  = tid >> 1;            // 0..127
    int c0 = (tid & 1) * 32;      // 0 or 32
    const size_t arow = (m0 + r) * GK;
    const size_t wrow = (size_t)(n0 + r) * GK;

    uint32_t sb = smem_u32(smh);
    uint32_t aSmemRow = (uint32_t)(r * SA + c0) * 2;   // byte offset within a plane

    // ldmatrix per-lane address components (element units)
    int ln  = lane & 7;
    int sel = lane >> 3;
    int aoff = (m_off + ln + (sel & 1) * 8) * SA + (sel >> 1) * 8;
    int half = (lane >> 3) & 1;
    int boff = (n_off + (lane & 7)) * SA + half * 8;

    // Prologue: cp.async A chunk 0 into buf 0
#pragma unroll
    for (int i = 0; i < 4; i++) {
        CP_ASYNC16(sb + 0 * SM_PLANE + aSmemRow + 16 * i, &Ahi[arow + c0 + 8 * i]);
        CP_ASYNC16(sb + 1 * SM_PLANE + aSmemRow + 16 * i, &Alo[arow + c0 + 8 * i]);
    }
    CP_COMMIT();

    for (int ch = 0; ch < 4; ch++) {
        int kb = ch * 64 + c0;
        int buf = ch & 1;

        // cp.async next chunk's A into the other buffer
        if (ch < 3) {
            int kb2 = (ch + 1) * 64 + c0;
            uint32_t nb = sb + ((ch + 1) & 1) * 2 * SM_PLANE + aSmemRow;
#pragma unroll
            for (int i = 0; i < 4; i++) {
                CP_ASYNC16(nb + 16 * i,            &Ahi[arow + kb2 + 8 * i]);
                CP_ASYNC16(nb + SM_PLANE + 16 * i, &Alo[arow + kb2 + 8 * i]);
            }
        }
        CP_COMMIT();

        // W: pre-split bf16 planes, plain LDG.128 + STS.128
#pragma unroll
        for (int i = 0; i < 4; i++) {
            uint4 wh = *(const uint4*)&Whi[wrow + kb + 8 * i];
            uint4 wl = *(const uint4*)&Wlo[wrow + kb + 8 * i];
            *(uint4*)&sWhi[r * SA + c0 + 8 * i] = wh;
            *(uint4*)&sWlo[r * SA + c0 + 8 * i] = wl;
        }

        // Wait for this chunk's A (next chunk's group may stay pending)
        if (ch < 3) { CP_WAIT(1); } else { CP_WAIT(0); }
        __syncthreads();

        uint32_t aHiBase = sb + buf * 2 * SM_PLANE;
        uint32_t aLoBase = aHiBase + SM_PLANE;

#pragma unroll
        for (int kk = 0; kk < 4; kk++) {
            uint32_t afh[4][4], afl[4][4], bfr[4][2];
#pragma unroll
            for (int mt = 0; mt < 4; mt++) {
                uint32_t addr = aHiBase + (uint32_t)(aoff + mt * 16 * SA + kk * 16) * 2;
                asm volatile(
                    "ldmatrix.sync.aligned.m8n8.x4.shared.b16 {%0,%1,%2,%3}, [%4];"
                    : "=r"(afh[mt][0]), "=r"(afh[mt][1]), "=r"(afh[mt][2]), "=r"(afh[mt][3])
                    : "r"(addr));
            }
#pragma unroll
            for (int nt = 0; nt < 4; nt++) {
                uint32_t addr = sb + 4 * SM_PLANE + (uint32_t)(boff + nt * 8 * SA + kk * 16) * 2;
                asm volatile(
                    "ldmatrix.sync.aligned.m8n8.x2.shared.b16 {%0,%1}, [%2];"
                    : "=r"(bfr[nt][0]), "=r"(bfr[nt][1]) : "r"(addr));
            }
            // term: Ahi * Whi
#pragma unroll
            for (int mt = 0; mt < 4; mt++)
#pragma unroll
                for (int nt = 0; nt < 4; nt++)
                    asm volatile(
                        "mma.sync.aligned.m16n8k16.row.col.f32.bf16.bf16.f32 "
                        "{%0,%1,%2,%3}, {%4,%5,%6,%7}, {%8,%9}, {%0,%1,%2,%3};"
                        : "+f"(acc[mt][nt][0]), "+f"(acc[mt][nt][1]),
                          "+f"(acc[mt][nt][2]), "+f"(acc[mt][nt][3])
                        : "r"(afh[mt][0]), "r"(afh[mt][1]), "r"(afh[mt][2]), "r"(afh[mt][3]),
                          "r"(bfr[nt][0]), "r"(bfr[nt][1]));
            // Alo fragments
#pragma unroll
            for (int mt = 0; mt < 4; mt++) {
                uint32_t addr = aLoBase + (uint32_t)(aoff + mt * 16 * SA + kk * 16) * 2;
                asm volatile(
                    "ldmatrix.sync.aligned.m8n8.x4.shared.b16 {%0,%1,%2,%3}, [%4];"
                    : "=r"(afl[mt][0]), "=r"(afl[mt][1]), "=r"(afl[mt][2]), "=r"(afl[mt][3])
                    : "r"(addr));
            }
            // term: Alo * Whi (reuses bfr)
#pragma unroll
            for (int mt = 0; mt < 4; mt++)
#pragma unroll
                for (int nt = 0; nt < 4; nt++)
                    asm volatile(
                        "mma.sync.aligned.m16n8k16.row.col.f32.bf16.bf16.f32 "
                        "{%0,%1,%2,%3}, {%4,%5,%6,%7}, {%8,%9}, {%0,%1,%2,%3};"
                        : "+f"(acc[mt][nt][0]), "+f"(acc[mt][nt][1]),
                          "+f"(acc[mt][nt][2]), "+f"(acc[mt][nt][3])
                        : "r"(afl[mt][0]), "r"(afl[mt][1]), "r"(afl[mt][2]), "r"(afl[mt][3]),
                          "r"(bfr[nt][0]), "r"(bfr[nt][1]));
            // Wlo fragments (overwrite bfr; Whi dead)
#pragma unroll
            for (int nt = 0; nt < 4; nt++) {
                uint32_t addr = sb + 5 * SM_PLANE + (uint32_t)(boff + nt * 8 * SA + kk * 16) * 2;
                asm volatile(
                    "ldmatrix.sync.aligned.m8n8.x2.shared.b16 {%0,%1}, [%2];"
                    : "=r"(bfr[nt][0]), "=r"(bfr[nt][1]) : "r"(addr));
            }
            // term: Ahi * Wlo
#pragma unroll
            for (int mt = 0; mt < 4; mt++)
#pragma unroll
                for (int nt = 0; nt < 4; nt++)
                    asm volatile(
                        "mma.sync.aligned.m16n8k16.row.col.f32.bf16.bf16.f32 "
                        "{%0,%1,%2,%3}, {%4,%5,%6,%7}, {%8,%9}, {%0,%1,%2,%3};"
                        : "+f"(acc[mt][nt][0]), "+f"(acc[mt][nt][1]),
                          "+f"(acc[mt][nt][2]), "+f"(acc[mt][nt][3])
                        : "r"(afh[mt][0]), "r"(afh[mt][1]), "r"(afh[mt][2]), "r"(afh[mt][3]),
                          "r"(bfr[nt][0]), "r"(bfr[nt][1]));
        }
        __syncthreads();   // W planes / A buffer reuse safe after all LDSM done
    }

    // Epilogue (streaming stores; xg is read-once later)
    int cr  = lane >> 2;
    int cc2 = (lane & 3) * 2;
#pragma unroll
    for (int nt = 0; nt < 4; nt++) {
        int n = n0 + n_off + nt * 8 + cc2;
        float2 bq = *(const float2*)&bias[n];
#pragma unroll
        for (int mt = 0; mt < 4; mt++) {
            size_t m = m0 + m_off + mt * 16 + cr;
            float2 o0 = make_float2(acc[mt][nt][0] + bq.x, acc[mt][nt][1] + bq.y);
            float2 o1 = make_float2(acc[mt][nt][2] + bq.x, acc[mt][nt][3] + bq.y);
            __stcs((float2*)&C[m * GG + n],       o0);
            __stcs((float2*)&C[(m + 8) * GG + n], o1);
        }
    }
}

// ---------------------------------------------------------------------------
// GRU scan: role-structured, race-free two-__syncthreads protocol,
// f32x2 reduction tree, unconditional guarded prefetch (xg has guard rows).
// grid = 128, 384 threads. g<256: r/z producer; g>=256: n gate + h update.
// ---------------------------------------------------------------------------
__global__ __launch_bounds__(384, 1) void gru_scan(
    const float* __restrict__ xgF, const float* __restrict__ xgR,
    const float* __restrict__ whhF, const float* __restrict__ bhhF,
    const float* __restrict__ whhR, const float* __restrict__ bhhR,
    unsigned short* __restrict__ outHi, unsigned short* __restrict__ outLo)
{
    int bb  = blockIdx.x >> 1;
    int dir = blockIdx.x & 1;
    const float* xg  = dir ? xgR  : xgF;
    const float* whh = dir ? whhR : whhF;
    const float* bhh = dir ? bhhR : bhhF;

    int g = threadIdx.x;
    int j = g & 127;

    u64 w2[64];
    {
        const double2* wrow = (const double2*)(whh + (size_t)g * HH);
#pragma unroll
        for (int i = 0; i < 32; i++) {
            double2 v = wrow[i];
            w2[2*i+0] = d2u(v.x);
            w2[2*i+1] = d2u(v.y);
        }
    }
    float bh = bhh[g];

    __shared__ __align__(16) float hs[HH];
    __shared__ float rz[2 * HH];
    if (g < HH) hs[g] = 0.0f;

    const float* xp = xg + (size_t)bb * TT * GG + (size_t)(dir ? (TT - 1) : 0) * GG + g;
    const ptrdiff_t xstep = dir ? -(ptrdiff_t)GG : (ptrdiff_t)GG;

    size_t oidx = (size_t)bb * TT * 256 + (size_t)(dir ? (TT - 1) : 0) * 256
                + (size_t)dir * HH + j;
    const ptrdiff_t ostep = dir ? -(ptrdiff_t)256 : (ptrdiff_t)256;

    float xv = __ldg(xp);
    xp += xstep;
    __syncthreads();

    const double2* hsd = (const double2*)hs;
    bool is_rz = (g < 2 * HH);

    for (int t = 0; t < TT; t++) {
        // Unconditional prefetch (guard rows make the last-iter read safe)
        float xv_next = __ldg(xp);

        u64 a0 = 0ull, a1 = 0ull, a2 = 0ull, a3 = 0ull;
#pragma unroll
        for (int i = 0; i < 16; i++) {
            double2 h0 = hsd[2*i];
            double2 h1 = hsd[2*i+1];
            a0 = ffma2(w2[4*i+0], d2u(h0.x), a0);
            a1 = ffma2(w2[4*i+1], d2u(h0.y), a1);
            a2 = ffma2(w2[4*i+2], d2u(h1.x), a2);
            a3 = ffma2(w2[4*i+3], d2u(h1.y), a3);
        }
        u64 s = addf2(addf2(a0, a1), addf2(a2, a3));
        float2 sp = unpack2(s);
        float acc = sp.x + sp.y + bh;

        if (is_rz) {
            rz[g] = sigf(acc + xv);
        }
        __syncthreads();   // rz visible to n-threads

        if (!is_rz) {
            float r  = rz[j];
            float z  = rz[j + HH];
            float n  = tanh_fast(fmaf(r, acc, xv));   // xv = xn here
            float hp = hs[j];
            float hn = fmaf(z, hp - n, n);
            hs[j] = hn;
            __nv_bfloat16 bhi = __float2bfloat16(hn);
            __nv_bfloat16 blo = __float2bfloat16(hn - __bfloat162float(bhi));
            outHi[oidx] = __bfloat16_as_ushort(bhi);
            outLo[oidx] = __bfloat16_as_ushort(blo);
        }
        __syncthreads();   // hs visible to ALL threads for next matvec

        xv = xv_next;
        xp += xstep;
        oidx += ostep;
    }
}

// ---------------------------------------------------------------------------
// Final FC: reads h1 = hi + lo planes
// ---------------------------------------------------------------------------
__global__ __launch_bounds__(256) void fc_kernel(
    const unsigned short* __restrict__ hHi,
    const unsigned short* __restrict__ hLo,
    const float* __restrict__ fw,   // [2][256]
    const float* __restrict__ fb,   // [2]
    float* __restrict__ out)        // [rows][2]
{
    int row  = blockIdx.x * 8 + (threadIdx.x >> 5);
    int lane = threadIdx.x & 31;
    size_t base = (size_t)row * 256;
    float a0 = 0.f, a1 = 0.f;
#pragma unroll
    for (int i = 0; i < 8; i++) {
        int k = lane + 32 * i;
        float v = __bfloat162float(__ushort_as_bfloat16(hHi[base + k]))
                + __bfloat162float(__ushort_as_bfloat16(hLo[base + k]));
        a0 = fmaf(v, fw[k],       a0);
        a1 = fmaf(v, fw[256 + k], a1);
    }
#pragma unroll
    for (int off = 16; off; off >>= 1) {
        a0 += __shfl_xor_sync(0xffffffffu, a0, off);
        a1 += __shfl_xor_sync(0xffffffffu, a1, off);
    }
    if (lane == 0) {
        out[(size_t)row * 2 + 0] = a0 + fb[0];
        out[(size_t)row * 2 + 1] = a1 + fb[1];
    }
}

// ---------------------------------------------------------------------------
// Launch
// ---------------------------------------------------------------------------
extern "C" void kernel_launch(void* const* d_in, const int* in_sizes, int n_in,
                              void* d_out, int out_size)
{
    const float* x        = (const float*)d_in[0];
    const float* w_ih_l0  = (const float*)d_in[1];
    const float* w_hh_l0  = (const float*)d_in[2];
    const float* b_ih_l0  = (const float*)d_in[3];
    const float* b_hh_l0  = (const float*)d_in[4];
    const float* w_ih_l0r = (const float*)d_in[5];
    const float* w_hh_l0r = (const float*)d_in[6];
    const float* b_ih_l0r = (const float*)d_in[7];
    const float* b_hh_l0r = (const float*)d_in[8];
    const float* w_ih_l1  = (const float*)d_in[9];
    const float* w_hh_l1  = (const float*)d_in[10];
    const float* b_ih_l1  = (const float*)d_in[11];
    const float* b_hh_l1  = (const float*)d_in[12];
    const float* w_ih_l1r = (const float*)d_in[13];
    const float* w_hh_l1r = (const float*)d_in[14];
    const float* b_ih_l1r = (const float*)d_in[15];
    const float* b_hh_l1r = (const float*)d_in[16];
    const float* fc_w     = (const float*)d_in[17];
    const float* fc_b     = (const float*)d_in[18];
    float* out = (float*)d_out;

    float *xgFr, *xgRr;
    unsigned short *hHi, *hLo, *wHi, *wLo;
    cudaGetSymbolAddress((void**)&xgFr, g_xgF_raw);
    cudaGetSymbolAddress((void**)&xgRr, g_xgR_raw);
    cudaGetSymbolAddress((void**)&hHi, g_hHi);
    cudaGetSymbolAddress((void**)&hLo, g_hLo);
    cudaGetSymbolAddress((void**)&wHi, g_wHi);
    cudaGetSymbolAddress((void**)&wLo, g_wLo);
    float* xgF = xgFr + GG;   // logical base (guard row below and above)
    float* xgR = xgRr + GG;

    static int smem_set = 0;
    const int HM_SMEM = 6 * SM_PLANE;   // 110592 B
    if (!smem_set) {
        cudaFuncSetAttribute(hmma_gemm, cudaFuncAttributeMaxDynamicSharedMemorySize, HM_SMEM);
        smem_set = 1;
    }

    // W pre-split for layer-1 projections (both directions)
    wsplit<<<WN / 256, 256>>>(w_ih_l1, w_ih_l1r, wHi, wLo);

    // Layer 0 input projections (K = 18)
    dim3 gGrid(BTR / 64, GG / 64);
    gemm_tn_bias<<<gGrid, 256>>>(x, DIN, w_ih_l0,  b_ih_l0,  xgF, GG, BTR, GG, DIN);
    gemm_tn_bias<<<gGrid, 256>>>(x, DIN, w_ih_l0r, b_ih_l0r, xgR, GG, BTR, GG, DIN);

    // Layer 0 scan -> h0 bf16 hi/lo planes
    gru_scan<<<BB * 2, GG>>>(xgF, xgR, w_hh_l0, b_hh_l0, w_hh_l0r, b_hh_l0r, hHi, hLo);

    // Layer 1 input projections (K = 256): tensor-core GEMM via mma.sync
    dim3 tcGrid(BTR / 128, GG / 128);  // 1024 x 3
    hmma_gemm<<<tcGrid, 256, HM_SMEM>>>(hHi, hLo, wHi,      wLo,      b_ih_l1,  xgF);
    hmma_gemm<<<tcGrid, 256, HM_SMEM>>>(hHi, hLo, wHi + WN, wLo + WN, b_ih_l1r, xgR);

    // Layer 1 scan -> h1 planes
    gru_scan<<<BB * 2, GG>>>(xgF, xgR, w_hh_l1, b_hh_l1, w_hh_l1r, b_hh_l1r, hHi, hLo);

    // Final FC
    fc_kernel<<<BTR / 8, 256>>>(hHi, hLo, fc_w, fc_b, out);
}